// round 5
// baseline (speedup 1.0000x reference)
#include <cuda_runtime.h>
#include <cstdint>
#include <cstddef>

#define B_   2
#define P_   8192
#define NNB  24
#define C1_  32
#define C2_  32
#define K_   13
#define A_   12
#define DR_  (C2_*A_)   /* 384 */
#define CA_  (C1_*A_)   /* 384 */
#define BP_  (B_*P_)    /* 16384 */

#define CHUNK 24        /* K elems per stage (= 2 c-planes) */
#define CPK   16        /* chunks per k-segment */
#define NKS   3         /* k8 mma steps per chunk */
#define TCH   (K_*CPK)  /* 208 total chunks */
#define SA_   40        /* A_s row stride (floats) */
#define SB_   40        /* B_s row stride (floats) */

// ---- scratch (device globals; no allocation allowed) ----
__device__ float WTt_g[K_*DR_*CA_];  // [k][dr(384)][ca(384)], tf32-rounded (~7.7MB)
__device__ float md_g[BP_*3];        // mean_dir
__device__ float kpo_g[C2_*K_*3];    // normalized k_pos_ori [d][k][xyz]
__device__ float be_g[C2_*A_];       // bias_eff[d][r]

__device__ __forceinline__ uint32_t f2tf32(float x) {
    uint32_t u;
    asm("cvt.rna.tf32.f32 %0, %1;" : "=r"(u) : "f"(x));
    return u;
}
__device__ __forceinline__ uint32_t smem_u32(const void* p) {
    uint32_t a;
    asm("{ .reg .u64 t; cvta.to.shared.u64 t, %1; cvt.u32.u64 %0, t; }" : "=r"(a) : "l"(p));
    return a;
}
__device__ __forceinline__ void cp16(uint32_t dst, const void* src) {
    asm volatile("cp.async.cg.shared.global [%0], [%1], 16;" :: "r"(dst), "l"(src));
}
#define CP_COMMIT() asm volatile("cp.async.commit_group;" ::: "memory")
#define CP_WAIT1()  asm volatile("cp.async.wait_group 1;" ::: "memory")

__device__ __forceinline__ void mma_tf32(float& c0, float& c1, float& c2, float& c3,
                                         uint32_t a0, uint32_t a1, uint32_t a2, uint32_t a3,
                                         uint32_t b0, uint32_t b1) {
    asm volatile("mma.sync.aligned.m16n8k8.row.col.f32.tf32.tf32.f32 "
                 "{%0,%1,%2,%3}, {%4,%5,%6,%7}, {%8,%9}, {%0,%1,%2,%3};"
                 : "+f"(c0), "+f"(c1), "+f"(c2), "+f"(c3)
                 : "r"(a0), "r"(a1), "r"(a2), "r"(a3), "r"(b0), "r"(b1));
}

// ===================== prep kernels =====================
__global__ void build_wt(const float* __restrict__ W,
                         const float* __restrict__ kpw,
                         const int*   __restrict__ idx_map,
                         const int*   __restrict__ tivr,
                         const int*   __restrict__ tir) {
    int idx = blockIdx.x * blockDim.x + threadIdx.x;
    const int total = K_*DR_*CA_;
    for (; idx < total; idx += gridDim.x * blockDim.x) {
        int ca = idx % CA_;
        int t  = idx / CA_;
        int n  = t % DR_;
        int k  = t / DR_;
        int d = n / A_, r = n % A_;
        int c = ca / A_, a = ca % A_;
        int j = idx_map[tivr[r*K_ + k]*A_ + tir[r*A_ + a]];
        float v = W[(d*C1_ + c)*36 + j] * kpw[d*36 + j];
        ((uint32_t*)WTt_g)[idx] = f2tf32(v);   // pre-round B to tf32
    }
}

__global__ void mean_dir_k(const int* __restrict__ nbr_idx,
                           const float* __restrict__ verts) {
    int bp = blockIdx.x * blockDim.x + threadIdx.x;
    if (bp >= BP_) return;
    int b = bp >> 13;
    int p = bp & (P_-1);
    const float* vb = verts + b * P_ * 3;
    float vx = vb[p*3+0], vy = vb[p*3+1], vz = vb[p*3+2];
    float sx = 0.f, sy = 0.f, sz = 0.f;
    const int* ni = nbr_idx + bp * NNB;
#pragma unroll 4
    for (int n = 0; n < NNB; n++) {
        int q = ni[n];
        float dx = vb[q*3+0] - vx;
        float dy = vb[q*3+1] - vy;
        float dz = vb[q*3+2] - vz;
        float nrm = sqrtf(dx*dx + dy*dy + dz*dz);
        float s = 1.0f / fmaxf(nrm, 1e-12f);
        sx += dx*s; sy += dy*s; sz += dz*s;
    }
    const float inv = 1.0f / (float)NNB;
    md_g[bp*3+0] = sx * inv;
    md_g[bp*3+1] = sy * inv;
    md_g[bp*3+2] = sz * inv;
}

__global__ void prep_small(const float* __restrict__ kpw,
                           const float* __restrict__ vs,
                           const int*   __restrict__ idx_map,
                           const int*   __restrict__ tivr,
                           const float* __restrict__ bias,
                           const int*   __restrict__ lvl) {
    int t = threadIdx.x;
    if (t < C2_*K_) {
        int d = t / K_, k = t % K_;
        float s0 = 0.f, s1 = 0.f, s2 = 0.f;
        for (int a = 0; a < A_; a++) {
            float w = kpw[d*36 + idx_map[k*A_ + a]];
            s0 += w * vs[a*3+0];
            s1 += w * vs[a*3+1];
            s2 += w * vs[a*3+2];
        }
        float nrm = sqrtf(s0*s0 + s1*s1 + s2*s2);
        float inv = 1.0f / fmaxf(nrm, 1e-12f);
        kpo_g[t*3+0] = s0*inv;
        kpo_g[t*3+1] = s1*inv;
        kpo_g[t*3+2] = s2*inv;
    }
    if (t < C2_*A_) {
        int d = t / A_, r = t % A_;
        float s = 0.f;
        for (int k = 0; k < K_; k++)
            s += bias[d*5 + lvl[tivr[r*K_ + k]]];
        be_g[t] = s;
    }
}

// ===================== main mma.sync tf32 kernel =====================
// smem (floats):
//   A_s [2][128][40] @0       (10240)  raw f32 A chunk (HW-truncated tf32)
//   B_s [2][192][40] @10240   (15360)  tf32 B chunk
//   ACC [128][200]   @25600   (25600)  per-CTA output accumulator
//   PW  [128][17]    @51200   (2176)
//   MD  [128][3]     @53376   (384)
//   KPO [16][13][3]  @53760   (624)
//   BE  [192]        @54384   (192)
#define OFF_A   0
#define OFF_B   10240
#define OFF_ACC 25600
#define OFF_PW  51200
#define OFF_MD  53376
#define OFF_KPO 53760
#define OFF_BE  54384
#define SMEM_FLOATS 54576
#define SMEM_BYTES (SMEM_FLOATS*4)

__global__ __launch_bounds__(256, 1) void equi_mma(const float* __restrict__ fm,
                                                   float* __restrict__ out) {
    extern __shared__ float s[];
    float* A_s = s + OFF_A;
    float* B_s = s + OFF_B;
    float* ACC = s + OFF_ACC;
    float* PW  = s + OFF_PW;
    float* MD  = s + OFF_MD;
    float* KPO = s + OFF_KPO;
    float* BE  = s + OFF_BE;
    const uint32_t sA = smem_u32(A_s);
    const uint32_t sB = smem_u32(B_s);

    const int tid  = threadIdx.x;
    const int wid  = tid >> 5;
    const int lane = tid & 31;
    const int gid  = lane >> 2;     // 0..7
    const int tig  = lane & 3;      // 0..3

    const int Ntile = blockIdx.x;        // 0..1
    const int Mtile = blockIdx.y;        // 0..127
    const int b  = Mtile >> 6;
    const int p0 = (Mtile & 63) << 7;
    const int n0 = Ntile * 192;
    const int d0 = Ntile * 16;

    // warp grid 2(m) x 4(n): warp tile 64m x 48n
    const int m0w = (wid & 1) * 64;
    const int n0w = (wid >> 1) * 48;

    // stage small tables
    for (int i = tid; i < 128*3; i += 256) MD[i]  = md_g[(size_t)Mtile*128*3 + i];
    for (int i = tid; i < 16*K_*3; i += 256) KPO[i] = kpo_g[d0*(K_*3) + i];
    if (tid < 192) BE[tid] = be_g[d0*A_ + tid];

    const float* fmb = fm + (size_t)b * C1_ * K_ * P_ * A_;

    float acc[4][6][4];
#pragma unroll
    for (int mt = 0; mt < 4; mt++)
#pragma unroll
        for (int nt = 0; nt < 6; nt++)
#pragma unroll
            for (int q = 0; q < 4; q++) acc[mt][nt][q] = 0.f;

    // A copy mapping: thread -> (row = tid&127, cseg = tid>>7), 3 x 16B
    const int rowA = tid & 127;
    const int csA  = tid >> 7;

    auto issue_copies = [&](int k, int j, int st) {
        // A: 128 rows x 24 cols (2 c-planes)
        {
            int c = j*2 + csA;
            const float* src = fmb + ((size_t)(c*K_ + k)*P_ + p0 + rowA)*A_;
            uint32_t dst = sA + (uint32_t)(st*128*SA_ + rowA*SA_ + csA*12)*4u;
#pragma unroll
            for (int q = 0; q < 3; q++)
                cp16(dst + q*16u, src + q*4);
        }
        // B: 192 rows x 24 cols
        const float* wk = WTt_g + (size_t)k*(DR_*CA_) + (size_t)n0*CA_ + j*CHUNK;
#pragma unroll
        for (int o = tid; o < 1152; o += 256) {
            int row = o / 6;
            int q   = o - row*6;
            uint32_t dst = sB + (uint32_t)(st*192*SB_ + row*SB_ + q*4)*4u;
            cp16(dst, wk + (size_t)row*CA_ + q*4);
        }
    };

    // prologue
    issue_copies(0, 0, 0);
    CP_COMMIT();

    int k = 0, j = 0;
    for (int t = 0; t < TCH; t++) {
        const int st = t & 1;
        // issue next chunk into the other buffer (mma of t-1 finished before
        // the barrier that ended iteration t-1)
        int t2 = t + 1;
        if (t2 < TCH) {
            int k2 = t2 >> 4, j2 = t2 & 15;
            issue_copies(k2, j2, t2 & 1);
        }
        CP_COMMIT();
        CP_WAIT1();            // chunk t landed
        __syncthreads();       // visible to all warps

        if (j == 0) {
            // per-k pw table
#pragma unroll
            for (int i = 0; i < 8; i++) {
                int e  = i*256 + tid;
                int m  = e & 127;
                int dl = e >> 7;
                const float* kp = KPO + (dl*K_ + k)*3;
                float w = MD[m*3+0]*kp[0] + MD[m*3+1]*kp[1] + MD[m*3+2]*kp[2];
                PW[m*17 + dl] = fmaxf(w, 0.f);
            }
        }

        const float* Ab = A_s + st*128*SA_;
        const float* Bb = B_s + st*192*SB_;
#pragma unroll
        for (int ks = 0; ks < NKS; ks++) {
            const int col = ks*8 + tig*2;
            uint32_t bb[6][2];
#pragma unroll
            for (int nt = 0; nt < 6; nt++) {
                float2 v = *(const float2*)&Bb[(n0w + nt*8 + gid)*SB_ + col];
                bb[nt][0] = __float_as_uint(v.x);
                bb[nt][1] = __float_as_uint(v.y);
            }
#pragma unroll
            for (int mt = 0; mt < 4; mt++) {
                int rb = m0w + mt*16 + gid;
                float2 alo = *(const float2*)&Ab[rb*SA_ + col];
                float2 ahi = *(const float2*)&Ab[(rb+8)*SA_ + col];
                uint32_t a0 = __float_as_uint(alo.x);
                uint32_t a1 = __float_as_uint(ahi.x);
                uint32_t a2 = __float_as_uint(alo.y);
                uint32_t a3 = __float_as_uint(ahi.y);
#pragma unroll
                for (int nt = 0; nt < 6; nt++)
                    mma_tf32(acc[mt][nt][0], acc[mt][nt][1], acc[mt][nt][2], acc[mt][nt][3],
                             a0, a1, a2, a3, bb[nt][0], bb[nt][1]);
            }
        }

        if (j == CPK-1) {
            // end of k-segment: fold pw into ACC (thread-private cells)
#pragma unroll
            for (int mt = 0; mt < 4; mt++) {
                int r0 = m0w + mt*16 + gid;
                int r1 = r0 + 8;
#pragma unroll
                for (int nt = 0; nt < 6; nt++) {
                    int n  = n0w + nt*8 + tig*2;
                    int dl = n / 12;
                    float pw0 = PW[r0*17 + dl];
                    float pw1 = PW[r1*17 + dl];
                    float2* c0p = (float2*)&ACC[r0*200 + n];
                    float2* c1p = (float2*)&ACC[r1*200 + n];
                    if (k == 0) {
                        *c0p = make_float2(pw0*acc[mt][nt][0], pw0*acc[mt][nt][1]);
                        *c1p = make_float2(pw1*acc[mt][nt][2], pw1*acc[mt][nt][3]);
                    } else {
                        float2 c0 = *c0p, c1 = *c1p;
                        c0.x = fmaf(pw0, acc[mt][nt][0], c0.x);
                        c0.y = fmaf(pw0, acc[mt][nt][1], c0.y);
                        c1.x = fmaf(pw1, acc[mt][nt][2], c1.x);
                        c1.y = fmaf(pw1, acc[mt][nt][3], c1.y);
                        *c0p = c0; *c1p = c1;
                    }
                    acc[mt][nt][0] = 0.f; acc[mt][nt][1] = 0.f;
                    acc[mt][nt][2] = 0.f; acc[mt][nt][3] = 0.f;
                }
            }
        }

        __syncthreads();       // protect buffer st from overwrite at t+2
        j++;
        if (j == CPK) { j = 0; k++; }
    }

    // ---- final: bias + relu, store out[b, d, p, r] ----
    {
        int m = tid & 127;
        int h = tid >> 7;
#pragma unroll
        for (int i = 0; i < 8; i++) {
            int dl = i*2 + h;
            float4 x0 = *(const float4*)&ACC[m*200 + dl*12 + 0];
            float4 x1 = *(const float4*)&ACC[m*200 + dl*12 + 4];
            float4 x2 = *(const float4*)&ACC[m*200 + dl*12 + 8];
            const float* bb = BE + dl*12;
            float4 y0 = make_float4(fmaxf(x0.x + bb[0], 0.f), fmaxf(x0.y + bb[1], 0.f),
                                    fmaxf(x0.z + bb[2], 0.f), fmaxf(x0.w + bb[3], 0.f));
            float4 y1 = make_float4(fmaxf(x1.x + bb[4], 0.f), fmaxf(x1.y + bb[5], 0.f),
                                    fmaxf(x1.z + bb[6], 0.f), fmaxf(x1.w + bb[7], 0.f));
            float4 y2 = make_float4(fmaxf(x2.x + bb[8], 0.f), fmaxf(x2.y + bb[9], 0.f),
                                    fmaxf(x2.z + bb[10], 0.f), fmaxf(x2.w + bb[11], 0.f));
            float* op = out + ((size_t)(b*C2_ + d0 + dl)*P_ + p0 + m)*A_;
            *(float4*)(op + 0) = y0;
            *(float4*)(op + 4) = y1;
            *(float4*)(op + 8) = y2;
        }
    }
}

// ---------------------------------------------------------------------------
extern "C" void kernel_launch(void* const* d_in, const int* in_sizes, int n_in,
                              void* d_out, int out_size) {
    const int*   nbr     = (const int*)  d_in[0];
    const float* verts   = (const float*)d_in[1];
    const float* fm      = (const float*)d_in[2];
    const float* W       = (const float*)d_in[3];
    const float* bias    = (const float*)d_in[4];
    const float* kpw     = (const float*)d_in[5];
    const float* vs      = (const float*)d_in[6];
    const int*   idx_map = (const int*)  d_in[7];
    const int*   tivr    = (const int*)  d_in[8];
    const int*   tir     = (const int*)  d_in[9];
    const int*   lvl     = (const int*)  d_in[10];
    float* out = (float*)d_out;

    static int smem_set = 0;
    if (!smem_set) {
        cudaFuncSetAttribute(equi_mma, cudaFuncAttributeMaxDynamicSharedMemorySize, SMEM_BYTES);
        smem_set = 1;
    }

    build_wt<<<512, 256>>>(W, kpw, idx_map, tivr, tir);
    mean_dir_k<<<BP_/256, 256>>>(nbr, verts);
    prep_small<<<1, 512>>>(kpw, vs, idx_map, tivr, bias, lvl);

    dim3 grid(2, 128);
    equi_mma<<<grid, 256, SMEM_BYTES>>>(fm, out);
}